// round 5
// baseline (speedup 1.0000x reference)
#include <cuda_runtime.h>

// HybridSurvivalQ: q_out = prod_{q=1..6} cos(x_q[q]+theta[q]); then 65->32->16->1
// MLP with ReLU. Weights live in __constant__ memory -> uniform-const port
// (LDCU, floor 1/SMSP, separate from LSU crossbar); zero LDS in the hot loop.
// R=2 rows/thread, packed fma.rn.f32x2 accumulators.

#define TPB 128
#define R   2

typedef unsigned long long u64;

__constant__ float cW1[65 * 32];
__constant__ float cB1[32];
__constant__ float cW2[32 * 16];
__constant__ float cB2[16];
__constant__ float cW3[16];
__constant__ float cB3[1];
__constant__ float cQP[7];

__device__ __forceinline__ u64 pack2(float lo, float hi) {
    u64 r;
    asm("mov.b64 %0, {%1, %2};" : "=l"(r) : "f"(lo), "f"(hi));
    return r;
}
__device__ __forceinline__ void unpack2(u64 v, float& lo, float& hi) {
    asm("mov.b64 {%0, %1}, %2;" : "=f"(lo), "=f"(hi) : "l"(v));
}
__device__ __forceinline__ u64 ffma2(u64 a, u64 b, u64 c) {
    u64 d;
    asm("fma.rn.f32x2 %0, %1, %2, %3;" : "=l"(d) : "l"(a), "l"(b), "l"(c));
    return d;
}

__global__ __launch_bounds__(TPB, 3)
void hybrid_mlp_kernel(const float* __restrict__ x_q,
                       const float* __restrict__ x_c,
                       float* __restrict__ out,
                       int B)
{
    long long gtid = (long long)blockIdx.x * TPB + threadIdx.x;
    int r0 = (int)(gtid * R);
    if (r0 >= B) return;

    int row1 = (r0 + 1 < B) ? r0 + 1 : r0;   // clamped; store guarded

    // ---- quantum part: q_out = prod_{q=1..6} cos(x_q[q] + theta[q]) ----
    float qv0, qv1;
    {
        const float* xq0 = x_q + (long long)r0 * 7;
        const float* xq1 = x_q + (long long)row1 * 7;
        float p0 = 1.0f, p1 = 1.0f;
#pragma unroll
        for (int k = 1; k < 7; k++) {
            float t = cQP[k];
            p0 *= __cosf(xq0[k] + t);
            p1 *= __cosf(xq1[k] + t);
        }
        qv0 = p0; qv1 = p1;
    }

    // ---- layer 1: 65 -> 32, packed accumulators, 2 rows ----
    u64 acc0[16], acc1[16];
    const u64* bb1 = (const u64*)cB1;
#pragma unroll
    for (int k = 0; k < 16; k++) { acc0[k] = bb1[k]; acc1[k] = bb1[k]; }

    {   // input feature 0 = q_out
        u64 x0 = pack2(qv0, qv0);
        u64 x1 = pack2(qv1, qv1);
        const u64* w = (const u64*)cW1;
#pragma unroll
        for (int k = 0; k < 16; k++) {
            u64 ww = w[k];
            acc0[k] = ffma2(x0, ww, acc0[k]);
            acc1[k] = ffma2(x1, ww, acc1[k]);
        }
    }

    const float4* xc0 = (const float4*)(x_c + (long long)r0 * 64);
    const float4* xc1 = (const float4*)(x_c + (long long)row1 * 64);

#pragma unroll 4
    for (int j4 = 0; j4 < 16; j4++) {
        float4 v0 = xc0[j4];
        float4 v1 = xc1[j4];
        float a0[4] = {v0.x, v0.y, v0.z, v0.w};
        float a1[4] = {v1.x, v1.y, v1.z, v1.w};
#pragma unroll
        for (int s = 0; s < 4; s++) {
            int j = 1 + j4 * 4 + s;
            u64 x0 = pack2(a0[s], a0[s]);
            u64 x1 = pack2(a1[s], a1[s]);
            const u64* w = (const u64*)(cW1 + j * 32);
#pragma unroll
            for (int k = 0; k < 16; k++) {
                u64 ww = w[k];
                acc0[k] = ffma2(x0, ww, acc0[k]);
                acc1[k] = ffma2(x1, ww, acc1[k]);
            }
        }
    }

    // ---- relu + layer 2: 32 -> 16 (read relu'd halves straight from acc) ----
    u64 a20[8], a21[8];
    const u64* bb2 = (const u64*)cB2;
#pragma unroll
    for (int k = 0; k < 8; k++) { a20[k] = bb2[k]; a21[k] = bb2[k]; }

#pragma unroll
    for (int j = 0; j < 32; j++) {
        float lo, hi, h;
        unpack2(acc0[j >> 1], lo, hi);
        h = fmaxf((j & 1) ? hi : lo, 0.0f);
        u64 x0 = pack2(h, h);
        unpack2(acc1[j >> 1], lo, hi);
        h = fmaxf((j & 1) ? hi : lo, 0.0f);
        u64 x1 = pack2(h, h);

        const u64* w = (const u64*)(cW2 + j * 16);
#pragma unroll
        for (int k = 0; k < 8; k++) {
            u64 ww = w[k];
            a20[k] = ffma2(x0, ww, a20[k]);
            a21[k] = ffma2(x1, ww, a21[k]);
        }
    }

    // ---- relu + layer 3: 16 -> 1 ----
    float s0 = cB3[0], s1 = cB3[0];
#pragma unroll
    for (int k = 0; k < 8; k++) {
        float w0 = cW3[2 * k], w1 = cW3[2 * k + 1];
        float lo, hi;
        unpack2(a20[k], lo, hi);
        s0 += fmaxf(lo, 0.0f) * w0 + fmaxf(hi, 0.0f) * w1;
        unpack2(a21[k], lo, hi);
        s1 += fmaxf(lo, 0.0f) * w0 + fmaxf(hi, 0.0f) * w1;
    }

    out[r0] = s0;
    if (r0 + 1 < B) out[r0 + 1] = s1;
}

extern "C" void kernel_launch(void* const* d_in, const int* in_sizes, int n_in,
                              void* d_out, int out_size)
{
    const float* x_q = (const float*)d_in[0];
    const float* x_c = (const float*)d_in[1];
    float* out = (float*)d_out;

    // Stage weights into constant memory (async D2D copies — graph-capturable,
    // no allocation). Done every call: deterministic.
    cudaMemcpyToSymbolAsync(cQP, d_in[2], 7 * sizeof(float), 0, cudaMemcpyDeviceToDevice);
    cudaMemcpyToSymbolAsync(cW1, d_in[3], 65 * 32 * sizeof(float), 0, cudaMemcpyDeviceToDevice);
    cudaMemcpyToSymbolAsync(cB1, d_in[4], 32 * sizeof(float), 0, cudaMemcpyDeviceToDevice);
    cudaMemcpyToSymbolAsync(cW2, d_in[5], 32 * 16 * sizeof(float), 0, cudaMemcpyDeviceToDevice);
    cudaMemcpyToSymbolAsync(cB2, d_in[6], 16 * sizeof(float), 0, cudaMemcpyDeviceToDevice);
    cudaMemcpyToSymbolAsync(cW3, d_in[7], 16 * sizeof(float), 0, cudaMemcpyDeviceToDevice);
    cudaMemcpyToSymbolAsync(cB3, d_in[8], 1 * sizeof(float), 0, cudaMemcpyDeviceToDevice);

    int B = in_sizes[0] / 7;                 // x_q is (B, 7)
    long long rows_per_blk = (long long)TPB * R;
    int grid = (int)((B + rows_per_blk - 1) / rows_per_blk);

    hybrid_mlp_kernel<<<grid, TPB>>>(x_q, x_c, out, B);
}